// round 12
// baseline (speedup 1.0000x reference)
#include <cuda_runtime.h>
#include <cstdint>
#include <math.h>

#define N_Q      4096
#define N_KV     32768
#define C_DIM    256
#define KNN      100
#define THREADS  256
#define MQ       4                 // queries per CTA (one per 2-warp team)
#define GRID     (N_Q / MQ)
#define LN_EPS   1e-5f
#define NGROUPS  (N_KV / 4)        // 8192 groups of 4 points
#define CAND_CAP 2048
#define QSCALE   2048.0f
#define SRANK    20                // sample rank (of 1024 samples)

typedef unsigned long long ull;

struct __align__(16) SmemLayout {
    unsigned int cand[MQ][CAND_CAP];            // 32 KB: (key16<<16) | idx
    __align__(16) unsigned int hist4[MQ][256];  // 4 KB pair-local histograms
    float        logits[MQ][112];
    float        wts[MQ][112];
    int          sel[MQ][128];
    int          eq_idx[MQ][64];
    float        eq_d2[MQ][64];
    float        qpos[MQ][4];                   // qx,qy,qz,|q|^2
    int          candn[MQ];
    float        thi[MQ];
    int          qflag[MQ];
    int          redo;
    int          psum[MQ][2];
    unsigned int bselp[MQ];
    int          kremp[MQ];
    int          n_less[MQ];
    int          eq_ctr[MQ];
    float        red1[MQ][2];
    float        red2[MQ][2];
};

extern __shared__ unsigned char smem_raw[];

__device__ __forceinline__ ull pack2(float lo, float hi) {
    ull r; asm("mov.b64 %0,{%1,%2};" : "=l"(r) : "f"(lo), "f"(hi)); return r;
}
__device__ __forceinline__ void unpack2(ull v, float& lo, float& hi) {
    asm("mov.b64 {%0,%1},%2;" : "=f"(lo), "=f"(hi) : "l"(v));
}
__device__ __forceinline__ ull fma2(ull a, ull b, ull c) {
    ull d; asm("fma.rn.f32x2 %0,%1,%2,%3;" : "=l"(d) : "l"(a), "l"(b), "l"(c)); return d;
}
__device__ __forceinline__ ull mul2(ull a, ull b) {
    ull d; asm("mul.rn.f32x2 %0,%1,%2;" : "=l"(d) : "l"(a), "l"(b)); return d;
}

__device__ __forceinline__ unsigned quant_key(float d2)
{
    float f = fmaxf(d2, 0.0f) * QSCALE;
    unsigned k = (unsigned)f;
    return k > 65535u ? 65535u : k;
}

#define PBAR(id) asm volatile("bar.sync %0, 64;" :: "r"(id) : "memory")

// 64-thread rank-select over this pair's 256-bin histogram.
// thread ptid owns bins 4*ptid..4*ptid+3. Writes s.bselp[m], s.kremp[m].
__device__ __forceinline__ void pair_rank_select(SmemLayout& s, int m, int krem,
                                                 int pw, int lane, int ptid, int barid)
{
    unsigned c0 = s.hist4[m][4 * ptid + 0];
    unsigned c1 = s.hist4[m][4 * ptid + 1];
    unsigned c2 = s.hist4[m][4 * ptid + 2];
    unsigned c3 = s.hist4[m][4 * ptid + 3];
    int local = (int)(c0 + c1 + c2 + c3);
    int x = local;
    #pragma unroll
    for (int o = 1; o < 32; o <<= 1) {
        int y = __shfl_up_sync(0xffffffffu, x, o);
        if (lane >= o) x += y;
    }
    if (lane == 31) s.psum[m][pw] = x;
    PBAR(barid);
    int incl = x + ((pw == 1) ? s.psum[m][0] : 0);
    int excl = incl - local;
    if (krem > excl && krem <= incl) {
        int cum = excl; unsigned b; int kr;
        if (krem <= cum + (int)c0)      { b = 4 * ptid + 0; kr = krem - cum; }
        else { cum += (int)c0;
          if (krem <= cum + (int)c1)    { b = 4 * ptid + 1; kr = krem - cum; }
          else { cum += (int)c1;
            if (krem <= cum + (int)c2)  { b = 4 * ptid + 2; kr = krem - cum; }
            else { cum += (int)c2;        b = 4 * ptid + 3; kr = krem - cum; } } }
        s.bselp[m] = b; s.kremp[m] = kr;
    }
    PBAR(barid);
}

__global__ __launch_bounds__(THREADS)
void sparse_attn_kernel(const float* __restrict__ q_feat,
                        const float* __restrict__ k_feat,
                        const float* __restrict__ v_feat,
                        const float* __restrict__ q_pos,
                        const float* __restrict__ k_pos,
                        const float* __restrict__ gamma,
                        const float* __restrict__ beta,
                        float* __restrict__ out)
{
    SmemLayout& s = *reinterpret_cast<SmemLayout*>(smem_raw);
    const int tid   = threadIdx.x;
    const int lane  = tid & 31;
    const int wid   = tid >> 5;
    const int qbase = blockIdx.x * MQ;

    const int pm    = wid >> 1;          // query 0..3 owned by this warp pair
    const int pw    = wid & 1;
    const int ptid  = (pw << 5) | lane;  // 0..63 within the pair
    const int barid = pm + 1;            // named barriers 1..4

    if (tid < MQ) {
        float x = q_pos[(qbase + tid) * 3 + 0];
        float y = q_pos[(qbase + tid) * 3 + 1];
        float z = q_pos[(qbase + tid) * 3 + 2];
        s.qpos[tid][0] = x; s.qpos[tid][1] = y; s.qpos[tid][2] = z;
        s.qpos[tid][3] = x * x + y * y + z * z;
        s.candn[tid] = 0; s.qflag[tid] = 1;
    }
    __syncthreads();

    // ======== Pair-parallel sample pass: per-query threshold ========
    {
        const float qxm = s.qpos[pm][0], qym = s.qpos[pm][1];
        const float qzm = s.qpos[pm][2], qsm = s.qpos[pm][3];
        reinterpret_cast<uint4*>(&s.hist4[pm][0])[ptid] = make_uint4(0, 0, 0, 0);
        PBAR(barid);
        #pragma unroll 4
        for (int k = 0; k < 16; k++) {
            int sj = 32 * (ptid + 64 * k);
            float kx = k_pos[3 * sj + 0];
            float ky = k_pos[3 * sj + 1];
            float kz = k_pos[3 * sj + 2];
            float d2 = qsm + kx * kx + ky * ky + kz * kz
                     - 2.0f * (qxm * kx + qym * ky + qzm * kz);
            atomicAdd(&s.hist4[pm][quant_key(d2) >> 8], 1u);
        }
        PBAR(barid);
        pair_rank_select(s, pm, SRANK, pw, lane, ptid, barid);
        if (ptid == 0)
            s.thi[pm] = (float)((s.bselp[pm] + 1u) << 8) * (1.0f / QSCALE);
    }
    __syncthreads();

    // ======== Main pass: f32x2 packed distances, 4 points / iter ========
    float Qsr[MQ], Thi[MQ], Tp[MQ];
    ull QX2[MQ], QY2[MQ], QZ2[MQ];
    bool act[MQ];
    #pragma unroll
    for (int m = 0; m < MQ; m++) {
        float qx = s.qpos[m][0], qy = s.qpos[m][1], qz = s.qpos[m][2];
        Qsr[m] = s.qpos[m][3];
        QX2[m] = pack2(-2.0f * qx, -2.0f * qx);
        QY2[m] = pack2(-2.0f * qy, -2.0f * qy);
        QZ2[m] = pack2(-2.0f * qz, -2.0f * qz);
        Thi[m] = s.thi[m];
        Tp[m]  = Thi[m] - Qsr[m];
        act[m] = true;
    }

    const float4* kp4 = reinterpret_cast<const float4*>(k_pos);
    for (int attempt = 0; attempt < 6; attempt++) {
        for (int g = tid; g < NGROUPS; g += THREADS) {
            float4 f0 = kp4[3 * g + 0];
            float4 f1 = kp4[3 * g + 1];
            float4 f2 = kp4[3 * g + 2];
            // pair0 = points 4g,4g+1 ; pair1 = points 4g+2,4g+3
            ull PX0 = pack2(f0.x, f0.w), PY0 = pack2(f0.y, f1.x), PZ0 = pack2(f0.z, f1.y);
            ull PX1 = pack2(f1.z, f2.y), PY1 = pack2(f1.w, f2.z), PZ1 = pack2(f2.x, f2.w);
            ull KK0 = fma2(PZ0, PZ0, fma2(PY0, PY0, mul2(PX0, PX0)));
            ull KK1 = fma2(PZ1, PZ1, fma2(PY1, PY1, mul2(PX1, PX1)));
            #pragma unroll
            for (int m = 0; m < MQ; m++) {
                if (!act[m]) continue;
                ull t0 = fma2(PZ0, QZ2[m], fma2(PY0, QY2[m], fma2(PX0, QX2[m], KK0)));
                ull t1 = fma2(PZ1, QZ2[m], fma2(PY1, QY2[m], fma2(PX1, QX2[m], KK1)));
                float a, b, c, d;
                unpack2(t0, a, b);
                unpack2(t1, c, d);
                // t = d2 - |q|^2 ; compare vs Tp = Thi - |q|^2
                if (a < Tp[m]) {
                    int p = atomicAdd(&s.candn[m], 1);
                    if (p < CAND_CAP)
                        s.cand[m][p] = (quant_key(a + Qsr[m]) << 16) | (unsigned)(4 * g + 0);
                }
                if (b < Tp[m]) {
                    int p = atomicAdd(&s.candn[m], 1);
                    if (p < CAND_CAP)
                        s.cand[m][p] = (quant_key(b + Qsr[m]) << 16) | (unsigned)(4 * g + 1);
                }
                if (c < Tp[m]) {
                    int p = atomicAdd(&s.candn[m], 1);
                    if (p < CAND_CAP)
                        s.cand[m][p] = (quant_key(c + Qsr[m]) << 16) | (unsigned)(4 * g + 2);
                }
                if (d < Tp[m]) {
                    int p = atomicAdd(&s.candn[m], 1);
                    if (p < CAND_CAP)
                        s.cand[m][p] = (quant_key(d + Qsr[m]) << 16) | (unsigned)(4 * g + 3);
                }
            }
        }
        __syncthreads();
        if (tid == 0) s.redo = 0;
        __syncthreads();
        if (tid < MQ && s.qflag[tid]) {
            int n = s.candn[tid];
            if (n >= KNN && n <= CAND_CAP) {
                s.qflag[tid] = 0;
            } else {
                s.candn[tid] = 0;
                s.thi[tid] = (n < KNN) ? s.thi[tid] * 2.0f : s.thi[tid] * 0.5f;
                atomicExch(&s.redo, 1);
            }
        }
        __syncthreads();
        if (!s.redo) break;
        #pragma unroll
        for (int m = 0; m < MQ; m++) {
            act[m] = s.qflag[m] != 0;
            Thi[m] = s.thi[m];
            Tp[m]  = Thi[m] - Qsr[m];
        }
        __syncthreads();
    }

    // ======== Pair-parallel exact selection ========
    {
        const float qxm = s.qpos[pm][0], qym = s.qpos[pm][1];
        const float qzm = s.qpos[pm][2], qsm = s.qpos[pm][3];

        int nc = s.candn[pm];
        if (nc > CAND_CAP) nc = CAND_CAP;

        int maxkey = (int)(s.thi[pm] * QSCALE);
        if (maxkey > 65535) maxkey = 65535;
        int sh = 0;
        while ((maxkey >> sh) > 255) sh++;

        reinterpret_cast<uint4*>(&s.hist4[pm][0])[ptid] = make_uint4(0, 0, 0, 0);
        if (ptid == 0) { s.n_less[pm] = 0; s.eq_ctr[pm] = 0; }
        PBAR(barid);
        for (int t = ptid; t < nc; t += 64)
            atomicAdd(&s.hist4[pm][(s.cand[pm][t] >> 16) >> sh], 1u);
        PBAR(barid);
        pair_rank_select(s, pm, KNN, pw, lane, ptid, barid);
        const unsigned bsel = s.bselp[pm];
        const int need_eq = s.kremp[pm];
        for (int t = ptid; t < nc; t += 64) {
            unsigned cw = s.cand[pm][t];
            unsigned b = (cw >> 16) >> sh;
            int j = (int)(cw & 0xffffu);
            if (b < bsel) {
                s.sel[pm][atomicAdd(&s.n_less[pm], 1)] = j;
            } else if (b == bsel) {
                int p = atomicAdd(&s.eq_ctr[pm], 1);
                if (p < 64) s.eq_idx[pm][p] = j;
            }
        }
        PBAR(barid);

        int ne = s.eq_ctr[pm]; if (ne > 64) ne = 64;
        if (ptid < ne) {
            int j = s.eq_idx[pm][ptid];
            float kx = k_pos[3 * j], ky = k_pos[3 * j + 1], kz = k_pos[3 * j + 2];
            float d2 = qsm + kx * kx + ky * ky + kz * kz
                     - 2.0f * (qxm * kx + qym * ky + qzm * kz);
            s.eq_d2[pm][ptid] = fmaxf(d2, 0.0f);
        }
        PBAR(barid);
        if (ptid == 0) {
            int nl = s.n_less[pm];
            int take = need_eq < ne ? need_eq : ne;
            for (int a = 0; a < take; ++a) {
                int best = a;
                for (int b = a + 1; b < ne; ++b) {
                    if (s.eq_d2[pm][b] < s.eq_d2[pm][best] ||
                        (s.eq_d2[pm][b] == s.eq_d2[pm][best] &&
                         s.eq_idx[pm][b] < s.eq_idx[pm][best]))
                        best = b;
                }
                float td = s.eq_d2[pm][a]; s.eq_d2[pm][a] = s.eq_d2[pm][best]; s.eq_d2[pm][best] = td;
                int   ti = s.eq_idx[pm][a]; s.eq_idx[pm][a] = s.eq_idx[pm][best]; s.eq_idx[pm][best] = ti;
                s.sel[pm][nl + a] = s.eq_idx[pm][a];
            }
        }
        PBAR(barid);
    }

    // ======== Pair-parallel epilogue (2 warps per query) ========
    const int qi = qbase + pm;

    // q_feat held in registers: lane owns channels lane*8 .. lane*8+7
    const float4* qf4 = reinterpret_cast<const float4*>(q_feat + (size_t)qi * C_DIM);
    float4 q0 = qf4[2 * lane + 0];
    float4 q1 = qf4[2 * lane + 1];

    // ---- logits: 50 neighbors per warp ----
    for (int j = pw; j < KNN; j += 2) {
        const float4* kr = reinterpret_cast<const float4*>(
            k_feat + (size_t)s.sel[pm][j] * C_DIM);
        float4 a0 = kr[2 * lane + 0];
        float4 a1 = kr[2 * lane + 1];
        float p = a0.x * q0.x + a0.y * q0.y + a0.z * q0.z + a0.w * q0.w
                + a1.x * q1.x + a1.y * q1.y + a1.z * q1.z + a1.w * q1.w;
        #pragma unroll
        for (int o = 16; o > 0; o >>= 1)
            p += __shfl_xor_sync(0xffffffffu, p, o);
        if (lane == 0) s.logits[pm][j] = p * 0.0625f;   // C^-0.5 = 1/16
    }
    PBAR(barid);

    // ---- softmax normalizers (computed redundantly by each warp) ----
    float mx = -INFINITY;
    #pragma unroll
    for (int u = 0; u < 4; u++) {
        int j = lane + 32 * u;
        if (j < KNN) mx = fmaxf(mx, s.logits[pm][j]);
    }
    #pragma unroll
    for (int o = 16; o > 0; o >>= 1)
        mx = fmaxf(mx, __shfl_xor_sync(0xffffffffu, mx, o));
    float ssum = 0.0f;
    #pragma unroll
    for (int u = 0; u < 4; u++) {
        int j = lane + 32 * u;
        if (j < KNN) ssum += expf(s.logits[pm][j] - mx);
    }
    #pragma unroll
    for (int o = 16; o > 0; o >>= 1)
        ssum += __shfl_xor_sync(0xffffffffu, ssum, o);
    float inv = 1.0f / ssum;
    #pragma unroll
    for (int j = ptid; j < KNN; j += 64)
        s.wts[pm][j] = expf(s.logits[pm][j] - mx) * inv;
    PBAR(barid);

    // ---- weighted V gather: thread owns channels 4*ptid..4*ptid+3 ----
    float4 acc = make_float4(0.f, 0.f, 0.f, 0.f);
    const float* wt = s.wts[pm];
    const int*   sl = s.sel[pm];
    #pragma unroll 5
    for (int j = 0; j < KNN; j++) {
        float w = wt[j];
        const float4 vr = *reinterpret_cast<const float4*>(
            v_feat + (size_t)sl[j] * C_DIM + 4 * ptid);
        acc.x += w * vr.x; acc.y += w * vr.y;
        acc.z += w * vr.z; acc.w += w * vr.w;
    }

    // res.at[arange].set(x) covers every row -> y = x + x = 2x
    float4 y = make_float4(2.f * acc.x, 2.f * acc.y, 2.f * acc.z, 2.f * acc.w);

    // ---- LayerNorm over C=256 (2-warp reduction) ----
    float s1 = y.x + y.y + y.z + y.w;
    float s2 = y.x * y.x + y.y * y.y + y.z * y.z + y.w * y.w;
    #pragma unroll
    for (int o = 16; o > 0; o >>= 1) {
        s1 += __shfl_xor_sync(0xffffffffu, s1, o);
        s2 += __shfl_xor_sync(0xffffffffu, s2, o);
    }
    if (lane == 0) { s.red1[pm][pw] = s1; s.red2[pm][pw] = s2; }
    PBAR(barid);
    float a = s.red1[pm][0] + s.red1[pm][1];
    float b = s.red2[pm][0] + s.red2[pm][1];
    float mean = a * (1.0f / C_DIM);
    float var  = b * (1.0f / C_DIM) - mean * mean;
    float rstd = rsqrtf(var + LN_EPS);

    const float4 g  = *reinterpret_cast<const float4*>(gamma + 4 * ptid);
    const float4 be = *reinterpret_cast<const float4*>(beta  + 4 * ptid);
    float4 o4;
    o4.x = (y.x - mean) * rstd * g.x + be.x;
    o4.y = (y.y - mean) * rstd * g.y + be.y;
    o4.z = (y.z - mean) * rstd * g.z + be.z;
    o4.w = (y.w - mean) * rstd * g.w + be.w;
    *reinterpret_cast<float4*>(out + (size_t)qi * C_DIM + 4 * ptid) = o4;
}

extern "C" void kernel_launch(void* const* d_in, const int* in_sizes, int n_in,
                              void* d_out, int out_size)
{
    // inputs: 0=res_feat (dead: scatter covers all rows), 1=q_feat, 2=k_feat,
    //         3=v_feat, 4=q_pos, 5=k_pos, 6=gamma, 7=beta
    const float* q_feat = (const float*)d_in[1];
    const float* k_feat = (const float*)d_in[2];
    const float* v_feat = (const float*)d_in[3];
    const float* q_pos  = (const float*)d_in[4];
    const float* k_pos  = (const float*)d_in[5];
    const float* gamma  = (const float*)d_in[6];
    const float* beta   = (const float*)d_in[7];
    float* out = (float*)d_out;

    const int smem_bytes = (int)sizeof(SmemLayout);
    cudaFuncSetAttribute(sparse_attn_kernel,
                         cudaFuncAttributeMaxDynamicSharedMemorySize, smem_bytes);
    sparse_attn_kernel<<<GRID, THREADS, smem_bytes>>>(
        q_feat, k_feat, v_feat, q_pos, k_pos, gamma, beta, out);
}

// round 15
// speedup vs baseline: 1.0265x; 1.0265x over previous
#include <cuda_runtime.h>
#include <cstdint>
#include <math.h>

#define N_Q      4096
#define N_KV     32768
#define C_DIM    256
#define KNN      100
#define THREADS  256
#define MQ       4                 // queries per CTA
#define GRID     (N_Q / MQ)
#define LN_EPS   1e-5f
#define NGROUPS  (N_KV / 4)        // 8192 groups of 4 points
#define CAND_CAP 1024
#define QSCALE   2048.0f
#define SRANK    16                // sample rank (of 1024 samples)

struct __align__(16) SmemLayout {
    unsigned int cand[MQ][CAND_CAP];   // 16 KB: (key16<<16) | idx
    float        logits[MQ][112];
    float        wts[MQ][112];
    int          sel[MQ][128];
    int          candn[MQ];
    float        thi[MQ];
    int          qflag[MQ];
    int          redo;
    unsigned int hist[256];
    int          wsum[8];
    unsigned int bsel;
    int          krem_s;
    float        qpos[MQ][4];          // qx,qy,qz,|q|^2
    int          eq_idx[64];
    float        eq_d2[64];
    int          n_less;
    int          eq_ctr;
    float        red1[MQ][2];
    float        red2[MQ][2];
};

extern __shared__ unsigned char smem_raw[];

// Parallel 256-bin rank-select: finds bin whose cumulative count crosses krem.
// Sets s.bsel = bin, s.krem_s = krem - exclusive_prefix(bin). Block collective.
__device__ __forceinline__ void bin_select(SmemLayout& s, int krem,
                                           int tid, int lane, int wid)
{
    int c = (int)s.hist[tid];
    int x = c;
    #pragma unroll
    for (int o = 1; o < 32; o <<= 1) {
        int y = __shfl_up_sync(0xffffffffu, x, o);
        if (lane >= o) x += y;
    }
    if (lane == 31) s.wsum[wid] = x;
    __syncthreads();
    if (tid == 0) {
        int acc = 0;
        #pragma unroll
        for (int ww = 0; ww < 8; ww++) { int t = s.wsum[ww]; s.wsum[ww] = acc; acc += t; }
    }
    __syncthreads();
    int incl = x + s.wsum[wid];
    int excl = incl - c;
    if (krem > excl && krem <= incl) { s.bsel = (unsigned)tid; s.krem_s = krem - excl; }
    __syncthreads();
}

__device__ __forceinline__ unsigned quant_key(float d2)
{
    float f = fmaxf(d2, 0.0f) * QSCALE;
    unsigned k = (unsigned)f;
    return k > 65535u ? 65535u : k;
}

__global__ __launch_bounds__(THREADS)
void sparse_attn_kernel(const float* __restrict__ q_feat,
                        const float* __restrict__ k_feat,
                        const float* __restrict__ v_feat,
                        const float* __restrict__ q_pos,
                        const float* __restrict__ k_pos,
                        const float* __restrict__ gamma,
                        const float* __restrict__ beta,
                        float* __restrict__ out)
{
    SmemLayout& s = *reinterpret_cast<SmemLayout*>(smem_raw);
    const int tid   = threadIdx.x;
    const int lane  = tid & 31;
    const int wid   = tid >> 5;
    const int qbase = blockIdx.x * MQ;

    if (tid < MQ) {
        float x = q_pos[(qbase + tid) * 3 + 0];
        float y = q_pos[(qbase + tid) * 3 + 1];
        float z = q_pos[(qbase + tid) * 3 + 2];
        s.qpos[tid][0] = x; s.qpos[tid][1] = y; s.qpos[tid][2] = z;
        s.qpos[tid][3] = x * x + y * y + z * z;
        s.candn[tid] = 0; s.qflag[tid] = 1;
    }
    __syncthreads();

    float Qx[MQ], Qy[MQ], Qz[MQ], Qs[MQ];
    #pragma unroll
    for (int m = 0; m < MQ; m++) {
        Qx[m] = s.qpos[m][0]; Qy[m] = s.qpos[m][1];
        Qz[m] = s.qpos[m][2]; Qs[m] = s.qpos[m][3];
    }

    // ---- Sample pass: per-query threshold from a 1/32 stride sample ----
    float sx[4], sy[4], sz[4];
    #pragma unroll
    for (int k = 0; k < 4; k++) {
        int j = 32 * (tid + 256 * k);
        sx[k] = k_pos[3 * j + 0];
        sy[k] = k_pos[3 * j + 1];
        sz[k] = k_pos[3 * j + 2];
    }
    for (int m = 0; m < MQ; m++) {
        s.hist[tid] = 0u;
        __syncthreads();
        #pragma unroll
        for (int k = 0; k < 4; k++) {
            float d2 = Qs[m] + sx[k] * sx[k] + sy[k] * sy[k] + sz[k] * sz[k]
                     - 2.0f * (Qx[m] * sx[k] + Qy[m] * sy[k] + Qz[m] * sz[k]);
            atomicAdd(&s.hist[quant_key(d2) >> 8], 1u);
        }
        __syncthreads();
        bin_select(s, SRANK, tid, lane, wid);
        if (tid == 0)
            s.thi[m] = (float)((s.bsel + 1u) << 8) * (1.0f / QSCALE);
        __syncthreads();
    }

    bool active[MQ];
    float Thi[MQ];
    #pragma unroll
    for (int m = 0; m < MQ; m++) { active[m] = true; Thi[m] = s.thi[m]; }

    // ---- Main pass: float4 k_pos stream, 4 points / iter, scalar math ----
    const float4* kp4 = reinterpret_cast<const float4*>(k_pos);
    for (int attempt = 0; attempt < 6; attempt++) {
        for (int g = tid; g < NGROUPS; g += THREADS) {
            float4 f0 = kp4[3 * g + 0];
            float4 f1 = kp4[3 * g + 1];
            float4 f2 = kp4[3 * g + 2];
            // A=(f0.x,f0.y,f0.z) B=(f0.w,f1.x,f1.y) C=(f1.z,f1.w,f2.x) D=(f2.y,f2.z,f2.w)
            float kka = f0.x * f0.x + f0.y * f0.y + f0.z * f0.z;
            float kkb = f0.w * f0.w + f1.x * f1.x + f1.y * f1.y;
            float kkc = f1.z * f1.z + f1.w * f1.w + f2.x * f2.x;
            float kkd = f2.y * f2.y + f2.z * f2.z + f2.w * f2.w;
            #pragma unroll
            for (int m = 0; m < MQ; m++) {
                if (!active[m]) continue;
                float d2a = Qs[m] + kka
                          - 2.0f * (Qx[m] * f0.x + Qy[m] * f0.y + Qz[m] * f0.z);
                float d2b = Qs[m] + kkb
                          - 2.0f * (Qx[m] * f0.w + Qy[m] * f1.x + Qz[m] * f1.y);
                float d2c = Qs[m] + kkc
                          - 2.0f * (Qx[m] * f1.z + Qy[m] * f1.w + Qz[m] * f2.x);
                float d2d = Qs[m] + kkd
                          - 2.0f * (Qx[m] * f2.y + Qy[m] * f2.z + Qz[m] * f2.w);
                if (d2a < Thi[m]) {
                    int p = atomicAdd(&s.candn[m], 1);
                    if (p < CAND_CAP)
                        s.cand[m][p] = (quant_key(d2a) << 16) | (unsigned)(4 * g + 0);
                }
                if (d2b < Thi[m]) {
                    int p = atomicAdd(&s.candn[m], 1);
                    if (p < CAND_CAP)
                        s.cand[m][p] = (quant_key(d2b) << 16) | (unsigned)(4 * g + 1);
                }
                if (d2c < Thi[m]) {
                    int p = atomicAdd(&s.candn[m], 1);
                    if (p < CAND_CAP)
                        s.cand[m][p] = (quant_key(d2c) << 16) | (unsigned)(4 * g + 2);
                }
                if (d2d < Thi[m]) {
                    int p = atomicAdd(&s.candn[m], 1);
                    if (p < CAND_CAP)
                        s.cand[m][p] = (quant_key(d2d) << 16) | (unsigned)(4 * g + 3);
                }
            }
        }
        __syncthreads();
        if (tid == 0) s.redo = 0;
        __syncthreads();
        if (tid < MQ && s.qflag[tid]) {
            int n = s.candn[tid];
            if (n >= KNN && n <= CAND_CAP) {
                s.qflag[tid] = 0;
            } else {
                s.candn[tid] = 0;
                s.thi[tid] = (n < KNN) ? s.thi[tid] * 2.0f : s.thi[tid] * 0.5f;
                atomicExch(&s.redo, 1);
            }
        }
        __syncthreads();
        if (!s.redo) break;
        #pragma unroll
        for (int m = 0; m < MQ; m++) {
            active[m] = s.qflag[m] != 0;
            Thi[m] = s.thi[m];
        }
        __syncthreads();
    }

    // ---- Per query: exact selection (block-wide, serial over m; cheap) ----
    for (int m = 0; m < MQ; m++) {
        const int nc_raw = s.candn[m];
        const int nc = nc_raw < CAND_CAP ? nc_raw : CAND_CAP;

        // dynamic shift so candidate keys fit 256 bins
        int maxkey = (int)(s.thi[m] * QSCALE);
        if (maxkey > 65535) maxkey = 65535;
        int sh = 0;
        while ((maxkey >> sh) > 255) sh++;

        s.hist[tid] = 0u;
        if (tid == 0) { s.n_less = 0; s.eq_ctr = 0; }
        __syncthreads();
        for (int t = tid; t < nc; t += THREADS)
            atomicAdd(&s.hist[(s.cand[m][t] >> 16) >> sh], 1u);
        __syncthreads();
        bin_select(s, KNN, tid, lane, wid);
        const unsigned bsel = s.bsel;
        const int need_eq = s.krem_s;
        __syncthreads();
        for (int t = tid; t < nc; t += THREADS) {
            unsigned cw = s.cand[m][t];
            unsigned b = (cw >> 16) >> sh;
            int j = (int)(cw & 0xffffu);
            if (b < bsel) {
                s.sel[m][atomicAdd(&s.n_less, 1)] = j;
            } else if (b == bsel) {
                int p = atomicAdd(&s.eq_ctr, 1);
                if (p < 64) s.eq_idx[p] = j;
            }
        }
        __syncthreads();

        // exact fp32 resolution of the boundary bin
        int ne = s.eq_ctr; if (ne > 64) ne = 64;
        if (tid < ne) {
            int j = s.eq_idx[tid];
            float kx = k_pos[3 * j], ky = k_pos[3 * j + 1], kz = k_pos[3 * j + 2];
            float d2 = Qs[m] + kx * kx + ky * ky + kz * kz
                     - 2.0f * (Qx[m] * kx + Qy[m] * ky + Qz[m] * kz);
            s.eq_d2[tid] = fmaxf(d2, 0.0f);
        }
        __syncthreads();
        if (tid == 0) {
            int nl = s.n_less;
            int take = need_eq < ne ? need_eq : ne;
            for (int a = 0; a < take; ++a) {
                int best = a;
                for (int b = a + 1; b < ne; ++b) {
                    if (s.eq_d2[b] < s.eq_d2[best] ||
                        (s.eq_d2[b] == s.eq_d2[best] && s.eq_idx[b] < s.eq_idx[best]))
                        best = b;
                }
                float td = s.eq_d2[a]; s.eq_d2[a] = s.eq_d2[best]; s.eq_d2[best] = td;
                int   ti = s.eq_idx[a]; s.eq_idx[a] = s.eq_idx[best]; s.eq_idx[best] = ti;
                s.sel[m][nl + a] = s.eq_idx[a];
            }
        }
        __syncthreads();
    }

    // ================= Parallel epilogues: 2 warps per query =================
    const int pm    = wid >> 1;          // query 0..3 owned by this warp pair
    const int pw    = wid & 1;           // warp index within the pair
    const int ptid  = (pw << 5) | lane;  // 0..63 within the pair
    const int qi    = qbase + pm;
    const int barid = pm + 1;            // named barriers 1..4

    // q_feat held in registers: lane owns channels lane*8 .. lane*8+7
    const float4* qf4 = reinterpret_cast<const float4*>(q_feat + (size_t)qi * C_DIM);
    float4 q0 = qf4[2 * lane + 0];
    float4 q1 = qf4[2 * lane + 1];

    // ---- logits: 50 neighbors per warp ----
    for (int j = pw; j < KNN; j += 2) {
        const float4* kr = reinterpret_cast<const float4*>(
            k_feat + (size_t)s.sel[pm][j] * C_DIM);
        float4 a0 = kr[2 * lane + 0];
        float4 a1 = kr[2 * lane + 1];
        float p = a0.x * q0.x + a0.y * q0.y + a0.z * q0.z + a0.w * q0.w
                + a1.x * q1.x + a1.y * q1.y + a1.z * q1.z + a1.w * q1.w;
        #pragma unroll
        for (int o = 16; o > 0; o >>= 1)
            p += __shfl_xor_sync(0xffffffffu, p, o);
        if (lane == 0) s.logits[pm][j] = p * 0.0625f;   // C^-0.5 = 1/16
    }
    asm volatile("bar.sync %0, %1;" :: "r"(barid), "r"(64) : "memory");

    // ---- softmax normalizers (computed redundantly by each warp) ----
    float mx = -INFINITY;
    #pragma unroll
    for (int u = 0; u < 4; u++) {
        int j = lane + 32 * u;
        if (j < KNN) mx = fmaxf(mx, s.logits[pm][j]);
    }
    #pragma unroll
    for (int o = 16; o > 0; o >>= 1)
        mx = fmaxf(mx, __shfl_xor_sync(0xffffffffu, mx, o));
    float ssum = 0.0f;
    #pragma unroll
    for (int u = 0; u < 4; u++) {
        int j = lane + 32 * u;
        if (j < KNN) ssum += expf(s.logits[pm][j] - mx);
    }
    #pragma unroll
    for (int o = 16; o > 0; o >>= 1)
        ssum += __shfl_xor_sync(0xffffffffu, ssum, o);
    float inv = 1.0f / ssum;
    #pragma unroll
    for (int j = ptid; j < KNN; j += 64)
        s.wts[pm][j] = expf(s.logits[pm][j] - mx) * inv;
    asm volatile("bar.sync %0, %1;" :: "r"(barid), "r"(64) : "memory");

    // ---- weighted V gather: thread owns channels 4*ptid..4*ptid+3 ----
    float4 acc = make_float4(0.f, 0.f, 0.f, 0.f);
    const float* wt = s.wts[pm];
    const int*   sl = s.sel[pm];
    #pragma unroll 5
    for (int j = 0; j < KNN; j++) {
        float w = wt[j];
        const float4 vr = *reinterpret_cast<const float4*>(
            v_feat + (size_t)sl[j] * C_DIM + 4 * ptid);
        acc.x += w * vr.x; acc.y += w * vr.y;
        acc.z += w * vr.z; acc.w += w * vr.w;
    }

    // res.at[arange].set(x) covers every row -> y = x + x = 2x
    float4 y = make_float4(2.f * acc.x, 2.f * acc.y, 2.f * acc.z, 2.f * acc.w);

    // ---- LayerNorm over C=256 (2-warp reduction) ----
    float s1 = y.x + y.y + y.z + y.w;
    float s2 = y.x * y.x + y.y * y.y + y.z * y.z + y.w * y.w;
    #pragma unroll
    for (int o = 16; o > 0; o >>= 1) {
        s1 += __shfl_xor_sync(0xffffffffu, s1, o);
        s2 += __shfl_xor_sync(0xffffffffu, s2, o);
    }
    if (lane == 0) { s.red1[pm][pw] = s1; s.red2[pm][pw] = s2; }
    asm volatile("bar.sync %0, %1;" :: "r"(barid), "r"(64) : "memory");
    float a = s.red1[pm][0] + s.red1[pm][1];
    float b = s.red2[pm][0] + s.red2[pm][1];
    float mean = a * (1.0f / C_DIM);
    float var  = b * (1.0f / C_DIM) - mean * mean;
    float rstd = rsqrtf(var + LN_EPS);

    const float4 g  = *reinterpret_cast<const float4*>(gamma + 4 * ptid);
    const float4 be = *reinterpret_cast<const float4*>(beta  + 4 * ptid);
    float4 o4;
    o4.x = (y.x - mean) * rstd * g.x + be.x;
    o4.y = (y.y - mean) * rstd * g.y + be.y;
    o4.z = (y.z - mean) * rstd * g.z + be.z;
    o4.w = (y.w - mean) * rstd * g.w + be.w;
    *reinterpret_cast<float4*>(out + (size_t)qi * C_DIM + 4 * ptid) = o4;
}

extern "C" void kernel_launch(void* const* d_in, const int* in_sizes, int n_in,
                              void* d_out, int out_size)
{
    // inputs: 0=res_feat (dead: scatter covers all rows), 1=q_feat, 2=k_feat,
    //         3=v_feat, 4=q_pos, 5=k_pos, 6=gamma, 7=beta
    const float* q_feat = (const float*)d_in[1];
    const float* k_feat = (const float*)d_in[2];
    const float* v_feat = (const float*)d_in[3];
    const float* q_pos  = (const float*)d_in[4];
    const float* k_pos  = (const float*)d_in[5];
    const float* gamma  = (const float*)d_in[6];
    const float* beta   = (const float*)d_in[7];
    float* out = (float*)d_out;

    const int smem_bytes = (int)sizeof(SmemLayout);
    cudaFuncSetAttribute(sparse_attn_kernel,
                         cudaFuncAttributeMaxDynamicSharedMemorySize, smem_bytes);
    sparse_attn_kernel<<<GRID, THREADS, smem_bytes>>>(
        q_feat, k_feat, v_feat, q_pos, k_pos, gamma, beta, out);
}